// round 9
// baseline (speedup 1.0000x reference)
#include <cuda_runtime.h>

#define B_DIM 32
#define L_DIM 4096
#define D_DIM 768
#define D4 (D_DIM / 4)      // 192 float4 per position
#define P_PER_BLK 8
#define SLICES 8            // marker scan slices per row
#define NSCAN (B_DIM * SLICES)          // 256 scan blocks
#define NBLK ((B_DIM * L_DIM) / P_PER_BLK)  // 16384 total blocks

// Scratch (no cudaMalloc allowed). All zero-initialized; the kernel restores
// the counters to zero on exit so graph replays see identical initial state.
__device__ int g_psep[NSCAN];
__device__ int g_peos[NSCAN];
__device__ int g_scan_count;   // 0 -> 256 -> 0 per launch
__device__ int g_exit_count;   // 0 -> NBLK -> 0 per launch

// Fused kernel: blocks 0..255 first scan one 512-token slice for the first
// token 4 (SEP) / token 2 (EOS) and publish partial mins; every block then
// polls until all 256 slices are published, reduces its row's partials, and
// writes 8 consecutive positions (192 threads = one full D-row).
// Token dtype: int32 or int64 (for int64 LE data every odd 32-bit word is 0,
// since tokens are in [2, 32000]); probe 4 odd words to decide.
__global__ void __launch_bounds__(192) fused_segment_embedding(
    const int* __restrict__ x32,
    const float4* __restrict__ W4,
    float4* __restrict__ out) {
    const int tid = threadIdx.x;
    const int bid = blockIdx.x;

    // ---- Phase 1: scan (blocks 0..NSCAN-1 only) ----
    if (bid < NSCAN) {
        const int b     = bid >> 3;          // / SLICES
        const int slice = bid & (SLICES - 1);
        const int l_lo  = slice * (L_DIM / SLICES);

        const bool is64 = (x32[1] == 0) & (x32[3] == 0) & (x32[5] == 0) & (x32[7] == 0);

        int lsep = L_DIM, leos = L_DIM;
        if (!is64) {
            // 512 tokens = 128 int4
            const int4* row = (const int4*)(x32 + (long long)b * L_DIM + l_lo);
            for (int k = tid; k < 128; k += 192) {
                const int4 v = row[k];
                const int base = l_lo + 4 * k;
                if (v.x == 4) lsep = min(lsep, base + 0);
                if (v.y == 4) lsep = min(lsep, base + 1);
                if (v.z == 4) lsep = min(lsep, base + 2);
                if (v.w == 4) lsep = min(lsep, base + 3);
                if (v.x == 2) leos = min(leos, base + 0);
                if (v.y == 2) leos = min(leos, base + 1);
                if (v.z == 2) leos = min(leos, base + 2);
                if (v.w == 2) leos = min(leos, base + 3);
            }
        } else {
            // 512 tokens = 256 int4 (tokens at .x / .z)
            const int4* row = (const int4*)(x32 + ((long long)b * L_DIM + l_lo) * 2);
            for (int k = tid; k < 256; k += 192) {
                const int4 v = row[k];
                const int base = l_lo + 2 * k;
                if (v.x == 4) lsep = min(lsep, base + 0);
                if (v.z == 4) lsep = min(lsep, base + 1);
                if (v.x == 2) leos = min(leos, base + 0);
                if (v.z == 2) leos = min(leos, base + 1);
            }
        }
        #pragma unroll
        for (int off = 16; off > 0; off >>= 1) {
            lsep = min(lsep, __shfl_down_sync(0xFFFFFFFFu, lsep, off));
            leos = min(leos, __shfl_down_sync(0xFFFFFFFFu, leos, off));
        }
        __shared__ int s_sep[6], s_eos[6];
        const int wid = tid >> 5;
        if ((tid & 31) == 0) { s_sep[wid] = lsep; s_eos[wid] = leos; }
        __syncthreads();
        if (tid == 0) {
            int ms = s_sep[0], me = s_eos[0];
            #pragma unroll
            for (int w = 1; w < 6; w++) {
                ms = min(ms, s_sep[w]);
                me = min(me, s_eos[w]);
            }
            g_psep[bid] = ms;
            g_peos[bid] = me;
            __threadfence();                 // partials visible before count
            atomicAdd(&g_scan_count, 1);
        }
    }

    // ---- Phase 2: wait for all slices, reduce this row's markers ----
    const int p0 = bid * P_PER_BLK;
    const int b  = p0 >> 12;                 // / L_DIM (blocks never straddle rows)
    const int l0 = p0 & (L_DIM - 1);

    __shared__ int sh_sep, sh_eos;
    if (tid == 0) {
        volatile int* vc = &g_scan_count;
        while (*vc != NSCAN) __nanosleep(64);
        __threadfence();                     // order partial reads after flag
        volatile int* vps = g_psep;
        volatile int* vpe = g_peos;
        int ms = L_DIM, me = L_DIM;
        #pragma unroll
        for (int s = 0; s < SLICES; s++) {
            ms = min(ms, vps[b * SLICES + s]);
            me = min(me, vpe[b * SLICES + s]);
        }
        sh_sep = ms;
        sh_eos = me;
    }
    __syncthreads();
    const int sep = sh_sep;
    const int eos = sh_eos;

    // ---- Phase 3: write 8 positions. Segments form runs 1..1,2..2,0..0 with
    // pairwise-distinct values, so seg(first)==seg(last) <=> uniform block. ----
    const int seg0 = (l0 < sep) ? 1 : ((l0 < eos) ? 2 : 0);
    const int lN   = l0 + P_PER_BLK - 1;
    const int segN = (lN < sep) ? 1 : ((lN < eos) ? 2 : 0);

    float4* __restrict__ o = out + (long long)p0 * D4 + tid;

    if (seg0 == segN) {                      // uniform block (>=99.4%)
        const float4 v = __ldg(W4 + seg0 * D4 + tid);
        #pragma unroll
        for (int j = 0; j < P_PER_BLK; j++)
            o[j * D4] = v;
    } else {                                 // boundary block (rare)
        #pragma unroll
        for (int j = 0; j < P_PER_BLK; j++) {
            const int l = l0 + j;
            const int seg = (l < sep) ? 1 : ((l < eos) ? 2 : 0);
            o[j * D4] = __ldg(W4 + seg * D4 + tid);
        }
    }

    // ---- Phase 4: replay-safe counter reset (last block to finish). ----
    __syncthreads();
    if (tid == 0) {
        const int d = atomicAdd(&g_exit_count, 1);
        if (d == NBLK - 1) {                 // everyone else is past all reads
            g_scan_count = 0;
            g_exit_count = 0;
            __threadfence();
        }
    }
}

extern "C" void kernel_launch(void* const* d_in, const int* in_sizes, int n_in,
                              void* d_out, int out_size) {
    // Identify inputs by element count: x has B*L, W has 3*D.
    const int* x;
    const float* W;
    if (in_sizes[0] == B_DIM * L_DIM) {
        x = (const int*)d_in[0];
        W = (const float*)d_in[1];
    } else {
        x = (const int*)d_in[1];
        W = (const float*)d_in[0];
    }

    fused_segment_embedding<<<NBLK, 192>>>(x, (const float4*)W, (float4*)d_out);
}

// round 10
// speedup vs baseline: 1.4522x; 1.4522x over previous
#include <cuda_runtime.h>

#define B_DIM 32
#define L_DIM 4096
#define D_DIM 768
#define D4 (D_DIM / 4)      // 192 float4 per position
#define P_PER_BLK 8
#define SLICES 8            // marker slices per row

// Scratch (no cudaMalloc allowed).
__device__ int g_psep[B_DIM * SLICES];
__device__ int g_peos[B_DIM * SLICES];

// Kernel 1: 256 blocks, each scans one 512-token slice for first token 4 (SEP)
// and first token 2 (EOS); writes partial mins, then triggers the dependent
// (write) kernel's launch via PDL. Handles int32 or int64 tokens: for int64 LE
// data every odd 32-bit word is 0 (tokens in [2, 32000]).
__global__ void __launch_bounds__(128) find_markers_partial(const int* __restrict__ x32) {
    const int b     = blockIdx.x >> 3;        // / SLICES
    const int slice = blockIdx.x & (SLICES - 1);
    const int l_lo  = slice * (L_DIM / SLICES);

    const bool is64 = (x32[1] == 0) & (x32[3] == 0) & (x32[5] == 0) & (x32[7] == 0);

    int lsep = L_DIM, leos = L_DIM;
    if (!is64) {
        // 512 tokens = 128 int4 -> exactly one load per thread
        const int4* row = (const int4*)(x32 + (long long)b * L_DIM + l_lo);
        const int k = threadIdx.x;
        const int4 v = row[k];
        const int base = l_lo + 4 * k;
        if (v.x == 4) lsep = min(lsep, base + 0);
        if (v.y == 4) lsep = min(lsep, base + 1);
        if (v.z == 4) lsep = min(lsep, base + 2);
        if (v.w == 4) lsep = min(lsep, base + 3);
        if (v.x == 2) leos = min(leos, base + 0);
        if (v.y == 2) leos = min(leos, base + 1);
        if (v.z == 2) leos = min(leos, base + 2);
        if (v.w == 2) leos = min(leos, base + 3);
    } else {
        // 512 tokens = 256 int4 -> two loads per thread (tokens at .x / .z)
        const int4* row = (const int4*)(x32 + ((long long)b * L_DIM + l_lo) * 2);
        #pragma unroll
        for (int it = 0; it < 2; it++) {
            const int k = threadIdx.x + it * 128;
            const int4 v = row[k];
            const int base = l_lo + 2 * k;
            if (v.x == 4) lsep = min(lsep, base + 0);
            if (v.z == 4) lsep = min(lsep, base + 1);
            if (v.x == 2) leos = min(leos, base + 0);
            if (v.z == 2) leos = min(leos, base + 1);
        }
    }
    #pragma unroll
    for (int off = 16; off > 0; off >>= 1) {
        lsep = min(lsep, __shfl_down_sync(0xFFFFFFFFu, lsep, off));
        leos = min(leos, __shfl_down_sync(0xFFFFFFFFu, leos, off));
    }
    __shared__ int s_sep[4], s_eos[4];
    const int wid = threadIdx.x >> 5;
    if ((threadIdx.x & 31) == 0) { s_sep[wid] = lsep; s_eos[wid] = leos; }
    __syncthreads();
    if (threadIdx.x == 0) {
        int ms = min(min(s_sep[0], s_sep[1]), min(s_sep[2], s_sep[3]));
        int me = min(min(s_eos[0], s_eos[1]), min(s_eos[2], s_eos[3]));
        g_psep[blockIdx.x] = ms;
        g_peos[blockIdx.x] = me;
        __threadfence();
        // PDL: this block's contribution is published; allow dependents.
        asm volatile("griddepcontrol.launch_dependents;");
    }
}

// Kernel 2: 192 threads = one D-row; each block writes 8 consecutive positions.
// Launched with programmatic stream serialization: blocks may start before the
// marker kernel finishes; griddepcontrol.wait blocks until the marker grid has
// completed and flushed memory, then thread 0 reduces the row's slice partials
// and broadcasts via smem. Segments form runs 1..1,2..2,0..0 with pairwise-
// distinct values, so seg(first)==seg(last) <=> whole block uniform.
__global__ void __launch_bounds__(192) write_embedding_kernel(
    const float4* __restrict__ W4, float4* __restrict__ out) {
    const int tid = threadIdx.x;
    const int p0  = blockIdx.x * P_PER_BLK;
    const int b   = p0 >> 12;           // / L_DIM (blocks never straddle rows)
    const int l0  = p0 & (L_DIM - 1);

    __shared__ int sh_sep, sh_eos;
    if (tid == 0) {
        // Wait for the marker kernel's results to be globally visible.
        asm volatile("griddepcontrol.wait;" ::: "memory");
        int ms = L_DIM, me = L_DIM;
        #pragma unroll
        for (int s = 0; s < SLICES; s++) {
            ms = min(ms, g_psep[b * SLICES + s]);
            me = min(me, g_peos[b * SLICES + s]);
        }
        sh_sep = ms;
        sh_eos = me;
    }
    __syncthreads();
    const int sep = sh_sep;
    const int eos = sh_eos;

    const int seg0 = (l0 < sep) ? 1 : ((l0 < eos) ? 2 : 0);
    const int lN   = l0 + P_PER_BLK - 1;
    const int segN = (lN < sep) ? 1 : ((lN < eos) ? 2 : 0);

    float4* __restrict__ o = out + (long long)p0 * D4 + tid;

    if (seg0 == segN) {                  // uniform block (>=99.4% of blocks)
        const float4 v = __ldg(W4 + seg0 * D4 + tid);
        #pragma unroll
        for (int j = 0; j < P_PER_BLK; j++)
            o[j * D4] = v;
    } else {                             // boundary block (rare)
        #pragma unroll
        for (int j = 0; j < P_PER_BLK; j++) {
            const int l = l0 + j;
            const int seg = (l < sep) ? 1 : ((l < eos) ? 2 : 0);
            o[j * D4] = __ldg(W4 + seg * D4 + tid);
        }
    }
}

extern "C" void kernel_launch(void* const* d_in, const int* in_sizes, int n_in,
                              void* d_out, int out_size) {
    // Identify inputs by element count: x has B*L, W has 3*D.
    const int* x;
    const float* W;
    if (in_sizes[0] == B_DIM * L_DIM) {
        x = (const int*)d_in[0];
        W = (const float*)d_in[1];
    } else {
        x = (const int*)d_in[1];
        W = (const float*)d_in[0];
    }

    find_markers_partial<<<B_DIM * SLICES, 128>>>(x);

    // Launch the write kernel with programmatic dependent launch so its blocks
    // ramp up while the marker kernel drains.
    cudaLaunchConfig_t cfg = {};
    cfg.gridDim  = dim3((B_DIM * L_DIM) / P_PER_BLK);   // 16384 blocks
    cfg.blockDim = dim3(192);
    cudaLaunchAttribute attr[1];
    attr[0].id = cudaLaunchAttributeProgrammaticStreamSerialization;
    attr[0].val.programmaticStreamSerializationAllowed = 1;
    cfg.attrs = attr;
    cfg.numAttrs = 1;
    cudaLaunchKernelEx(&cfg, write_embedding_kernel,
                       (const float4*)W, (float4*)d_out);
}